// round 1
// baseline (speedup 1.0000x reference)
#include <cuda_runtime.h>

// ---------------- problem constants ----------------
#define B_     4
#define C_     256
#define H_     128
#define W_     128
#define P_     (H_ * W_)      // 16384 pixels per batch
#define HEADS_ 8
#define DH_    32
#define BLK_   8
#define HALO_  3
#define WIN_   14
#define NKEY_  (WIN_ * WIN_)  // 196
#define NBH_   16
#define NB_    256            // blocks per image
#define QN_    64             // queries per block

// ---------------- scratch (device globals; no allocation allowed) ----------------
// g_qkv: [b][p][o] with o: 0..255 = q, 256..511 = k, 512..767 = v   (~201 MB)
__device__ float g_qkv[(size_t)B_ * P_ * 768];
// g_ctx: [b][c][p] channel-major                                     (~67 MB)
__device__ float g_ctx[(size_t)B_ * C_ * P_];

// =====================================================================
// Kernel 1: QKV projection.  out[p][o] = sum_c x[c][p] * W[o][c]
// per batch.  BM=128 (p), BN=64 (o), BK=16, 256 threads, 8x4 microtile.
// =====================================================================
__global__ __launch_bounds__(256) void qkv_gemm_k(
    const float* __restrict__ x,
    const float* __restrict__ wq,
    const float* __restrict__ wkv)
{
    __shared__ float As[16][128];   // [k][m=p]
    __shared__ float Bs[16][64];    // [k][n=o]

    const int pT  = blockIdx.x * 128;
    const int oT  = blockIdx.y * 64;
    const int b   = blockIdx.z;
    const int tid = threadIdx.x;
    const int m0  = (tid >> 4) * 4;   // 0..60 (rows m0..m0+3 and m0+64..m0+67)
    const int n0  = (tid & 15) * 4;   // 0..60

    const float* xb = x + (size_t)b * C_ * P_;

    float acc[8][4];
#pragma unroll
    for (int i = 0; i < 8; i++)
#pragma unroll
        for (int j = 0; j < 4; j++) acc[i][j] = 0.f;

    // B-tile loading assignment (weights, L2-resident)
    const int wn   = tid & 63;
    const int wk   = (tid >> 6) * 4;
    const int orow = oT + wn;
    const float* wrow = (orow < 256) ? (wq + orow * 256)
                                     : (wkv + (orow - 256) * 256);

    for (int k0 = 0; k0 < 256; k0 += 16) {
        // A tile: 16x128 from x (coalesced, float4)
#pragma unroll
        for (int t = 0; t < 2; t++) {
            int f  = tid + t * 256;       // float4 index 0..511
            int kk = f >> 5;
            int m4 = (f & 31) << 2;
            *(float4*)&As[kk][m4] =
                *(const float4*)&xb[(size_t)(k0 + kk) * P_ + pT + m4];
        }
        // B tile: 16x64 from weights
        {
            float4 wv = *(const float4*)&wrow[k0 + wk];
            Bs[wk + 0][wn] = wv.x;
            Bs[wk + 1][wn] = wv.y;
            Bs[wk + 2][wn] = wv.z;
            Bs[wk + 3][wn] = wv.w;
        }
        __syncthreads();

#pragma unroll
        for (int kk = 0; kk < 16; kk++) {
            float4 a0 = *(float4*)&As[kk][m0];
            float4 a1 = *(float4*)&As[kk][m0 + 64];
            float4 bv = *(float4*)&Bs[kk][n0];
            float a[8] = {a0.x, a0.y, a0.z, a0.w, a1.x, a1.y, a1.z, a1.w};
            float bb[4] = {bv.x, bv.y, bv.z, bv.w};
#pragma unroll
            for (int i = 0; i < 8; i++)
#pragma unroll
                for (int j = 0; j < 4; j++) acc[i][j] += a[i] * bb[j];
        }
        __syncthreads();
    }

#pragma unroll
    for (int i = 0; i < 8; i++) {
        int m = (i < 4) ? (m0 + i) : (m0 + 64 + (i - 4));
        float4 v = make_float4(acc[i][0], acc[i][1], acc[i][2], acc[i][3]);
        *(float4*)&g_qkv[((size_t)b * P_ + pT + m) * 768 + oT + n0] = v;
    }
}

// =====================================================================
// Kernel 2: halo attention. One CTA per (batch, block). 256 threads.
// Per head: stage q(64x32), k/v window(196x32) in smem, compute rel-pos
// bias, scores, softmax, ctx; write ctx channel-major to g_ctx.
// =====================================================================
// smem layout (floats)
#define OQ_   0                         // 64*33
#define OK_   (OQ_ + 64 * 33)           // 196*33
#define OV_   (OK_ + 196 * 33)          // 196*33
#define OS_   (OV_ + 196 * 33)          // 64*197
#define OBW_  (OS_ + 64 * 197)          // 64*14
#define OBH_  (OBW_ + 64 * 14)          // 64*14
#define ORH_  (OBH_ + 64 * 14)          // 27*32
#define ORW_  (ORH_ + 27 * 32)          // 27*32
#define SMEMF_ (ORW_ + 27 * 32)         // 31176 floats = 124704 B

__global__ __launch_bounds__(256) void halo_attn_k(
    const float* __restrict__ rel_h,
    const float* __restrict__ rel_w)
{
    extern __shared__ float sm[];
    float* sQ  = sm + OQ_;
    float* sK  = sm + OK_;
    float* sV  = sm + OV_;
    float* sS  = sm + OS_;
    float* sBW = sm + OBW_;
    float* sBH = sm + OBH_;
    float* sRH = sm + ORH_;
    float* sRW = sm + ORW_;

    const int b   = blockIdx.y;
    const int blk = blockIdx.x;
    const int bh  = blk >> 4;
    const int bw  = blk & 15;
    const int tid = threadIdx.x;
    const float scale = 0.1767766952966369f;  // 1/sqrt(32)

    // relative-position tables (reused by all heads)
    for (int i = tid; i < 27 * 32; i += 256) {
        sRH[i] = rel_h[i];
        sRW[i] = rel_w[i];
    }

    for (int hd = 0; hd < HEADS_; hd++) {
        __syncthreads();  // protect smem reuse (also orders rel-table load)

        // ---- load Q block: 64 x 32 ----
#pragma unroll
        for (int t = 0; t < 8; t++) {
            int idx = tid + t * 256;          // 0..2047
            int r = idx >> 5, d = idx & 31;
            int xq = r >> 3, yq = r & 7;
            int p = (bh * 8 + xq) * 128 + bw * 8 + yq;
            sQ[r * 33 + d] = g_qkv[((size_t)b * P_ + p) * 768 + hd * 32 + d];
        }
        // ---- load K,V window: 196 x 32 each (zero-padded halo) ----
        for (int idx = tid; idx < NKEY_ * 32; idx += 256) {
            int r = idx >> 5, d = idx & 31;
            int iw = r / 14, jw = r - iw * 14;
            int hp = bh * 8 - HALO_ + iw;
            int wp = bw * 8 - HALO_ + jw;
            float kv = 0.f, vv = 0.f;
            if (hp >= 0 && hp < H_ && wp >= 0 && wp < W_) {
                size_t base = ((size_t)b * P_ + hp * 128 + wp) * 768 + hd * 32 + d;
                kv = g_qkv[base + 256];
                vv = g_qkv[base + 512];
            }
            sK[r * 33 + d] = kv;
            sV[r * 33 + d] = vv;
        }
        __syncthreads();

        // ---- rel-pos bias: bw[qi][j], bh[qi][i] ----
        for (int idx = tid; idx < 64 * 14; idx += 256) {
            int qi = idx / 14, j = idx - qi * 14;
            int xq = qi >> 3, yq = qi & 7;
            const float* qrow = sQ + qi * 33;
            const float* rw = sRW + (j - yq + 13) * 32;
            const float* rh = sRH + (j - xq + 13) * 32;
            float aw = 0.f, ah = 0.f;
#pragma unroll
            for (int d = 0; d < 32; d++) {
                aw += qrow[d] * rw[d];
                ah += qrow[d] * rh[d];
            }
            sBW[idx] = aw;
            sBH[idx] = ah;
        }
        __syncthreads();

        // ---- scores: s[qi][kj] = scale * q.k + bw[qi][kj%14] + bh[qi][kj/14] ----
        for (int idx = tid; idx < QN_ * NKEY_; idx += 256) {
            int qi = idx / NKEY_, kj = idx - qi * NKEY_;
            const float* qrow = sQ + qi * 33;
            const float* krow = sK + kj * 33;
            float acc = 0.f;
#pragma unroll
            for (int d = 0; d < 32; d++) acc += qrow[d] * krow[d];
            int iw = kj / 14, jw = kj - iw * 14;
            sS[qi * 197 + kj] = acc * scale + sBW[qi * 14 + jw] + sBH[qi * 14 + iw];
        }
        __syncthreads();

        // ---- softmax per row (warp handles 8 rows) ----
        {
            int warp = tid >> 5, lane = tid & 31;
            for (int r = warp * 8; r < warp * 8 + 8; r++) {
                float* row = sS + r * 197;
                float m = -1e30f;
                for (int c = lane; c < NKEY_; c += 32) m = fmaxf(m, row[c]);
#pragma unroll
                for (int o = 16; o; o >>= 1) m = fmaxf(m, __shfl_xor_sync(0xffffffffu, m, o));
                float s = 0.f;
                for (int c = lane; c < NKEY_; c += 32) {
                    float e = __expf(row[c] - m);
                    row[c] = e;
                    s += e;
                }
#pragma unroll
                for (int o = 16; o; o >>= 1) s += __shfl_xor_sync(0xffffffffu, s, o);
                float inv = 1.f / s;
                for (int c = lane; c < NKEY_; c += 32) row[c] *= inv;
            }
        }
        __syncthreads();

        // ---- ctx: ctx[qi][d] = sum_kj att * v ; write channel-major ----
#pragma unroll
        for (int t = 0; t < 8; t++) {
            int idx = tid + t * 256;     // 0..2047
            int d = idx >> 6, qi = idx & 63;
            const float* srow = sS + qi * 197;
            float acc = 0.f;
            for (int kj = 0; kj < NKEY_; kj++)
                acc += srow[kj] * sV[kj * 33 + d];
            int xq = qi >> 3, yq = qi & 7;
            int p = (bh * 8 + xq) * 128 + bw * 8 + yq;
            g_ctx[((size_t)b * C_ + hd * 32 + d) * P_ + p] = acc;
        }
    }
}

// =====================================================================
// Kernel 3: FC epilogue.  out[b][o][p] = sum_c fc_w[o][c]*ctx[b][c][p] + fc_b[o]
// BM=64 (o), BN=128 (p), BK=16, 256 threads, 4x8 microtile.
// =====================================================================
__global__ __launch_bounds__(256) void fc_gemm_k(
    const float* __restrict__ fcw,
    const float* __restrict__ fcb,
    float* __restrict__ out)
{
    __shared__ float As[16][64];    // [k][m=o]
    __shared__ float Bs[16][128];   // [k][n=p]

    const int pT  = blockIdx.x * 128;
    const int oT  = blockIdx.y * 64;
    const int b   = blockIdx.z;
    const int tid = threadIdx.x;
    const int m0  = (tid >> 4) * 4;
    const int n0  = (tid & 15) * 4;

    float acc[4][8];
#pragma unroll
    for (int i = 0; i < 4; i++)
#pragma unroll
        for (int j = 0; j < 8; j++) acc[i][j] = 0.f;

    const int am = tid & 63;
    const int ak = (tid >> 6) * 4;
    const float* arow = fcw + (oT + am) * 256;
    const float* ctxb = g_ctx + (size_t)b * C_ * P_;

    for (int k0 = 0; k0 < 256; k0 += 16) {
        {
            float4 av = *(const float4*)&arow[k0 + ak];
            As[ak + 0][am] = av.x;
            As[ak + 1][am] = av.y;
            As[ak + 2][am] = av.z;
            As[ak + 3][am] = av.w;
        }
#pragma unroll
        for (int t = 0; t < 2; t++) {
            int f  = tid + t * 256;
            int kk = f >> 5;
            int n4 = (f & 31) << 2;
            *(float4*)&Bs[kk][n4] =
                *(const float4*)&ctxb[(size_t)(k0 + kk) * P_ + pT + n4];
        }
        __syncthreads();

#pragma unroll
        for (int kk = 0; kk < 16; kk++) {
            float4 av = *(float4*)&As[kk][m0];
            float4 b0 = *(float4*)&Bs[kk][n0];
            float4 b1 = *(float4*)&Bs[kk][n0 + 64];
            float a[4] = {av.x, av.y, av.z, av.w};
            float bb[8] = {b0.x, b0.y, b0.z, b0.w, b1.x, b1.y, b1.z, b1.w};
#pragma unroll
            for (int i = 0; i < 4; i++)
#pragma unroll
                for (int j = 0; j < 8; j++) acc[i][j] += a[i] * bb[j];
        }
        __syncthreads();
    }

#pragma unroll
    for (int i = 0; i < 4; i++) {
        int o = oT + m0 + i;
        float bias = fcb[o];
        float4 v0 = make_float4(acc[i][0] + bias, acc[i][1] + bias,
                                acc[i][2] + bias, acc[i][3] + bias);
        float4 v1 = make_float4(acc[i][4] + bias, acc[i][5] + bias,
                                acc[i][6] + bias, acc[i][7] + bias);
        float* orow = out + ((size_t)b * C_ + o) * P_ + pT;
        *(float4*)&orow[n0]      = v0;
        *(float4*)&orow[n0 + 64] = v1;
    }
}

// =====================================================================
extern "C" void kernel_launch(void* const* d_in, const int* in_sizes, int n_in,
                              void* d_out, int out_size)
{
    const float* x   = (const float*)d_in[0];
    const float* wq  = (const float*)d_in[1];
    const float* wkv = (const float*)d_in[2];
    const float* fcw = (const float*)d_in[3];
    const float* fcb = (const float*)d_in[4];
    const float* rh  = (const float*)d_in[5];
    const float* rw  = (const float*)d_in[6];
    float* out = (float*)d_out;

    cudaFuncSetAttribute(halo_attn_k,
                         cudaFuncAttributeMaxDynamicSharedMemorySize,
                         SMEMF_ * (int)sizeof(float));

    qkv_gemm_k<<<dim3(P_ / 128, 768 / 64, B_), 256>>>(x, wq, wkv);
    halo_attn_k<<<dim3(NB_, B_), 256, SMEMF_ * sizeof(float)>>>(rh, rw);
    fc_gemm_k<<<dim3(P_ / 128, C_ / 64, B_), 256>>>(fcw, fcb, out);
}

// round 2
// speedup vs baseline: 1.6655x; 1.6655x over previous
#include <cuda_runtime.h>

// ---------------- problem constants ----------------
#define B_     4
#define C_     256
#define H_     128
#define W_     128
#define P_     (H_ * W_)      // 16384 pixels per batch
#define HEADS_ 8
#define DH_    32
#define BLK_   8
#define HALO_  3
#define WIN_   14
#define NKEY_  (WIN_ * WIN_)  // 196
#define NKPAD_ 224            // padded key count (4 blocks of 56)
#define NB_    256            // blocks per image
#define QN_    64             // queries per block

// ---------------- scratch (device globals; no allocation allowed) ----------------
// g_qkv: [b][p][o] with o: 0..255 = q, 256..511 = k, 512..767 = v
__device__ float g_qkv[(size_t)B_ * P_ * 768];
// g_ctx: [b][c][p] channel-major
__device__ float g_ctx[(size_t)B_ * C_ * P_];

// =====================================================================
// Kernel 1: QKV projection.  out[p][o] = sum_c x[c][p] * W[o][c]
// BM=128 (p), BN=128 (o), BK=16, 256 threads, 8x8 microtile.
// =====================================================================
__global__ __launch_bounds__(256) void qkv_gemm_k(
    const float* __restrict__ x,
    const float* __restrict__ wq,
    const float* __restrict__ wkv)
{
    __shared__ float As[16][128];   // [k][m=p]
    __shared__ float Bs[16][128];   // [k][n=o]

    const int pT  = blockIdx.x * 128;
    const int oT  = blockIdx.y * 128;
    const int b   = blockIdx.z;
    const int tid = threadIdx.x;
    const int tx  = tid & 15;        // n group
    const int ty  = tid >> 4;        // m group
    const int m0  = ty * 4;
    const int n0  = tx * 4;

    const float* xb = x + (size_t)b * C_ * P_;

    float acc[8][8];
#pragma unroll
    for (int i = 0; i < 8; i++)
#pragma unroll
        for (int j = 0; j < 8; j++) acc[i][j] = 0.f;

    // weight row pointers for the two B-load slices
    const int ol0 = tid >> 2;            // 0..63
    const int ol1 = ol0 + 64;            // 64..127
    const int k4  = (tid & 3) << 2;      // 0,4,8,12
    const int or0 = oT + ol0;
    const int or1 = oT + ol1;
    const float* wr0 = (or0 < 256) ? (wq + or0 * 256) : (wkv + (or0 - 256) * 256);
    const float* wr1 = (or1 < 256) ? (wq + or1 * 256) : (wkv + (or1 - 256) * 256);

    for (int k0 = 0; k0 < 256; k0 += 16) {
        // A tile: 16x128 from x (coalesced float4)
#pragma unroll
        for (int t = 0; t < 2; t++) {
            int f  = tid + t * 256;       // float4 index 0..511
            int kk = f >> 5;
            int m4 = (f & 31) << 2;
            *(float4*)&As[kk][m4] =
                *(const float4*)&xb[(size_t)(k0 + kk) * P_ + pT + m4];
        }
        // B tile: 16x128 from weights (transpose on store)
        {
            float4 w0 = *(const float4*)&wr0[k0 + k4];
            float4 w1 = *(const float4*)&wr1[k0 + k4];
            Bs[k4 + 0][ol0] = w0.x; Bs[k4 + 1][ol0] = w0.y;
            Bs[k4 + 2][ol0] = w0.z; Bs[k4 + 3][ol0] = w0.w;
            Bs[k4 + 0][ol1] = w1.x; Bs[k4 + 1][ol1] = w1.y;
            Bs[k4 + 2][ol1] = w1.z; Bs[k4 + 3][ol1] = w1.w;
        }
        __syncthreads();

#pragma unroll
        for (int kk = 0; kk < 16; kk++) {
            float4 a0 = *(float4*)&As[kk][m0];
            float4 a1 = *(float4*)&As[kk][m0 + 64];
            float4 b0 = *(float4*)&Bs[kk][n0];
            float4 b1 = *(float4*)&Bs[kk][n0 + 64];
            float a[8] = {a0.x, a0.y, a0.z, a0.w, a1.x, a1.y, a1.z, a1.w};
            float bb[8] = {b0.x, b0.y, b0.z, b0.w, b1.x, b1.y, b1.z, b1.w};
#pragma unroll
            for (int i = 0; i < 8; i++)
#pragma unroll
                for (int j = 0; j < 8; j++) acc[i][j] += a[i] * bb[j];
        }
        __syncthreads();
    }

#pragma unroll
    for (int i = 0; i < 8; i++) {
        int m = (i < 4) ? (m0 + i) : (m0 + 64 + (i - 4));
        float* orow = &g_qkv[((size_t)b * P_ + pT + m) * 768 + oT];
        float4 v0 = make_float4(acc[i][0], acc[i][1], acc[i][2], acc[i][3]);
        float4 v1 = make_float4(acc[i][4], acc[i][5], acc[i][6], acc[i][7]);
        *(float4*)&orow[n0]      = v0;
        *(float4*)&orow[n0 + 64] = v1;
    }
}

// =====================================================================
// Kernel 2: halo attention. One CTA per (batch, block). 512 threads.
// Register-tiled score/ctx phases with broadcast-friendly warp layouts.
// =====================================================================
// smem layout (floats)
#define OQ_   0                           // 64*33
#define OK_   (OQ_ + 64 * 33)             // 224*33 (rows 196..223 are pad)
#define OV_   (OK_ + NKPAD_ * 33)         // 196*33
#define OS_   (OV_ + 196 * 33)            // 64*197
#define OBW_  (OS_ + 64 * 197)            // 64*14
#define OBH_  (OBW_ + 64 * 14)            // 64*14
#define ORH_  (OBH_ + 64 * 14)            // 27*32
#define ORW_  (ORH_ + 27 * 32)            // 27*32
#define SMEMF_ (ORW_ + 27 * 32)

__global__ __launch_bounds__(512) void halo_attn_k(
    const float* __restrict__ rel_h,
    const float* __restrict__ rel_w)
{
    extern __shared__ float sm[];
    float* sQ  = sm + OQ_;
    float* sK  = sm + OK_;
    float* sV  = sm + OV_;
    float* sS  = sm + OS_;
    float* sBW = sm + OBW_;
    float* sBH = sm + OBH_;
    float* sRH = sm + ORH_;
    float* sRW = sm + ORW_;

    const int b   = blockIdx.y;
    const int blk = blockIdx.x;
    const int bh  = blk >> 4;
    const int bw  = blk & 15;
    const int tid = threadIdx.x;
    const int w   = tid >> 5;
    const int lane = tid & 31;
    const float scale = 0.1767766952966369f;  // 1/sqrt(32)

    // relative-position tables (reused by all heads)
    for (int i = tid; i < 27 * 32; i += 512) {
        sRH[i] = rel_h[i];
        sRW[i] = rel_w[i];
    }

    for (int hd = 0; hd < HEADS_; hd++) {
        __syncthreads();  // protect smem reuse across iterations (and rel tables)

        // ---- load Q block: 64 x 32 ----
#pragma unroll
        for (int t = 0; t < 4; t++) {
            int idx = tid + t * 512;          // 0..2047
            int r = idx >> 5, d = idx & 31;
            int xq = r >> 3, yq = r & 7;
            int p = (bh * 8 + xq) * 128 + bw * 8 + yq;
            sQ[r * 33 + d] = g_qkv[((size_t)b * P_ + p) * 768 + hd * 32 + d];
        }
        // ---- load K,V window: 196 x 32 each (zero-padded halo) ----
        for (int idx = tid; idx < NKEY_ * 32; idx += 512) {
            int r = idx >> 5, d = idx & 31;
            int iw = r / 14, jw = r - iw * 14;
            int hp = bh * 8 - HALO_ + iw;
            int wp = bw * 8 - HALO_ + jw;
            float kv = 0.f, vv = 0.f;
            if (hp >= 0 && hp < H_ && wp >= 0 && wp < W_) {
                size_t base = ((size_t)b * P_ + hp * 128 + wp) * 768 + hd * 32 + d;
                kv = g_qkv[base + 256];
                vv = g_qkv[base + 512];
            }
            sK[r * 33 + d] = kv;
            sV[r * 33 + d] = vv;
        }
        __syncthreads();

        // ---- rel-pos bias: bw[qi][j], bh[qi][i] ----
        for (int idx = tid; idx < 64 * 14; idx += 512) {
            int qi = idx / 14, j = idx - qi * 14;
            int xq = qi >> 3, yq = qi & 7;
            const float* qrow = sQ + qi * 33;
            const float* rw = sRW + (j - yq + 13) * 32;
            const float* rh = sRH + (j - xq + 13) * 32;
            float aw = 0.f, ah = 0.f;
#pragma unroll
            for (int d = 0; d < 32; d++) {
                aw += qrow[d] * rw[d];
                ah += qrow[d] * rh[d];
            }
            sBW[idx] = aw;
            sBH[idx] = ah;
        }
        __syncthreads();

        // ---- scores: register-tiled 4q x 7k per thread ----
        {
            const int qb = w >> 2;            // 0..3  (16 q each)
            const int kb = w & 3;             // 0..3  (56 k each)
            const int qg = lane >> 3;         // 0..3
            const int kg = lane & 7;          // 0..7
            const int q0 = qb * 16 + qg * 4;
            const int k0 = kb * 56 + kg * 7;

            float acc[4][7];
#pragma unroll
            for (int i = 0; i < 4; i++)
#pragma unroll
                for (int j = 0; j < 7; j++) acc[i][j] = 0.f;

            const float* qp = sQ + q0 * 33;
            const float* kp = sK + k0 * 33;
#pragma unroll
            for (int d = 0; d < 32; d++) {
                float qv[4], kv[7];
#pragma unroll
                for (int i = 0; i < 4; i++) qv[i] = qp[i * 33 + d];
#pragma unroll
                for (int j = 0; j < 7; j++) kv[j] = kp[j * 33 + d];
#pragma unroll
                for (int i = 0; i < 4; i++)
#pragma unroll
                    for (int j = 0; j < 7; j++) acc[i][j] += qv[i] * kv[j];
            }
#pragma unroll
            for (int i = 0; i < 4; i++) {
                int qi = q0 + i;
#pragma unroll
                for (int j = 0; j < 7; j++) {
                    int kj = k0 + j;
                    if (kj < NKEY_) {
                        int r14 = kj / 14;
                        int c14 = kj - r14 * 14;
                        sS[qi * 197 + kj] = acc[i][j] * scale
                                          + sBW[qi * 14 + c14]
                                          + sBH[qi * 14 + r14];
                    }
                }
            }
        }
        __syncthreads();

        // ---- softmax per row (16 warps x 4 rows) ----
        {
            for (int r = w * 4; r < w * 4 + 4; r++) {
                float* row = sS + r * 197;
                float m = -1e30f;
                for (int c = lane; c < NKEY_; c += 32) m = fmaxf(m, row[c]);
#pragma unroll
                for (int o = 16; o; o >>= 1) m = fmaxf(m, __shfl_xor_sync(0xffffffffu, m, o));
                float s = 0.f;
                for (int c = lane; c < NKEY_; c += 32) {
                    float e = __expf(row[c] - m);
                    row[c] = e;
                    s += e;
                }
#pragma unroll
                for (int o = 16; o; o >>= 1) s += __shfl_xor_sync(0xffffffffu, s, o);
                float inv = 1.f / s;
                for (int c = lane; c < NKEY_; c += 32) row[c] *= inv;
            }
        }
        __syncthreads();

        // ---- ctx: register-tiled 2q x 2d per thread ----
        {
            const int qt = (w >> 1) * 4 + (lane >> 3);   // 0..31
            const int dt = (w & 1) * 8 + (lane & 7);     // 0..15
            const int q0 = qt * 2;
            const int d0 = dt * 2;

            float a00 = 0.f, a01 = 0.f, a10 = 0.f, a11 = 0.f;
            const float* s0p = sS + q0 * 197;
            const float* s1p = s0p + 197;
            const float* vp  = sV + d0;
#pragma unroll 4
            for (int k = 0; k < NKEY_; k++) {
                float s0 = s0p[k];
                float s1 = s1p[k];
                float v0 = vp[k * 33];
                float v1 = vp[k * 33 + 1];
                a00 += s0 * v0; a01 += s0 * v1;
                a10 += s1 * v0; a11 += s1 * v1;
            }
            int xq0 = q0 >> 3, yq0 = q0 & 7;
            int xq1 = (q0 + 1) >> 3, yq1 = (q0 + 1) & 7;
            int p0 = (bh * 8 + xq0) * 128 + bw * 8 + yq0;
            int p1 = (bh * 8 + xq1) * 128 + bw * 8 + yq1;
            size_t c0 = (size_t)b * C_ + hd * 32 + d0;
            g_ctx[c0 * P_ + p0]       = a00;
            g_ctx[(c0 + 1) * P_ + p0] = a01;
            g_ctx[c0 * P_ + p1]       = a10;
            g_ctx[(c0 + 1) * P_ + p1] = a11;
        }
    }
}

// =====================================================================
// Kernel 3: FC epilogue.  out[b][o][p] = sum_c fc_w[o][c]*ctx[b][c][p] + fc_b[o]
// BM=64 (o), BN=128 (p), BK=16, 256 threads, 4x8 microtile.
// =====================================================================
__global__ __launch_bounds__(256) void fc_gemm_k(
    const float* __restrict__ fcw,
    const float* __restrict__ fcb,
    float* __restrict__ out)
{
    __shared__ float As[16][64];    // [k][m=o]
    __shared__ float Bs[16][128];   // [k][n=p]

    const int pT  = blockIdx.x * 128;
    const int oT  = blockIdx.y * 64;
    const int b   = blockIdx.z;
    const int tid = threadIdx.x;
    const int m0  = (tid >> 4) * 4;
    const int n0  = (tid & 15) * 4;

    float acc[4][8];
#pragma unroll
    for (int i = 0; i < 4; i++)
#pragma unroll
        for (int j = 0; j < 8; j++) acc[i][j] = 0.f;

    const int am = tid & 63;
    const int ak = (tid >> 6) * 4;
    const float* arow = fcw + (oT + am) * 256;
    const float* ctxb = g_ctx + (size_t)b * C_ * P_;

    for (int k0 = 0; k0 < 256; k0 += 16) {
        {
            float4 av = *(const float4*)&arow[k0 + ak];
            As[ak + 0][am] = av.x;
            As[ak + 1][am] = av.y;
            As[ak + 2][am] = av.z;
            As[ak + 3][am] = av.w;
        }
#pragma unroll
        for (int t = 0; t < 2; t++) {
            int f  = tid + t * 256;
            int kk = f >> 5;
            int n4 = (f & 31) << 2;
            *(float4*)&Bs[kk][n4] =
                *(const float4*)&ctxb[(size_t)(k0 + kk) * P_ + pT + n4];
        }
        __syncthreads();

#pragma unroll
        for (int kk = 0; kk < 16; kk++) {
            float4 av = *(float4*)&As[kk][m0];
            float4 b0 = *(float4*)&Bs[kk][n0];
            float4 b1 = *(float4*)&Bs[kk][n0 + 64];
            float a[4] = {av.x, av.y, av.z, av.w};
            float bb[8] = {b0.x, b0.y, b0.z, b0.w, b1.x, b1.y, b1.z, b1.w};
#pragma unroll
            for (int i = 0; i < 4; i++)
#pragma unroll
                for (int j = 0; j < 8; j++) acc[i][j] += a[i] * bb[j];
        }
        __syncthreads();
    }

#pragma unroll
    for (int i = 0; i < 4; i++) {
        int o = oT + m0 + i;
        float bias = fcb[o];
        float4 v0 = make_float4(acc[i][0] + bias, acc[i][1] + bias,
                                acc[i][2] + bias, acc[i][3] + bias);
        float4 v1 = make_float4(acc[i][4] + bias, acc[i][5] + bias,
                                acc[i][6] + bias, acc[i][7] + bias);
        float* orow = out + ((size_t)b * C_ + o) * P_ + pT;
        *(float4*)&orow[n0]      = v0;
        *(float4*)&orow[n0 + 64] = v1;
    }
}

// =====================================================================
extern "C" void kernel_launch(void* const* d_in, const int* in_sizes, int n_in,
                              void* d_out, int out_size)
{
    const float* x   = (const float*)d_in[0];
    const float* wq  = (const float*)d_in[1];
    const float* wkv = (const float*)d_in[2];
    const float* fcw = (const float*)d_in[3];
    const float* fcb = (const float*)d_in[4];
    const float* rh  = (const float*)d_in[5];
    const float* rw  = (const float*)d_in[6];
    float* out = (float*)d_out;

    cudaFuncSetAttribute(halo_attn_k,
                         cudaFuncAttributeMaxDynamicSharedMemorySize,
                         SMEMF_ * (int)sizeof(float));

    qkv_gemm_k<<<dim3(P_ / 128, 6, B_), 256>>>(x, wq, wkv);
    halo_attn_k<<<dim3(NB_, B_), 512, SMEMF_ * sizeof(float)>>>(rh, rw);
    fc_gemm_k<<<dim3(P_ / 128, C_ / 64, B_), 256>>>(fcw, fcb, out);
}

// round 3
// speedup vs baseline: 1.6845x; 1.0114x over previous
#include <cuda_runtime.h>

// ---------------- problem constants ----------------
#define B_     4
#define C_     256
#define H_     128
#define W_     128
#define P_     (H_ * W_)      // 16384 pixels per batch
#define HEADS_ 8
#define DH_    32
#define BLK_   8
#define HALO_  3
#define WIN_   14
#define NKEY_  (WIN_ * WIN_)  // 196
#define NKPAD_ 224
#define NB_    256
#define QN_    64
#define KST_   36             // smem row stride (floats) for Q/K/V

// ---------------- scratch (device globals) ----------------
__device__ float g_qkv[(size_t)B_ * P_ * 768];   // [b][p][o] q|k|v
__device__ float g_ctx[(size_t)B_ * C_ * P_];    // [b][c][p]

// =====================================================================
// Kernel 1: QKV projection, ping-pong double buffered.
// out[p][o] = sum_c x[c][p] * W[o][c]. BM=128(p) BN=128(o) BK=16, 256thr.
// =====================================================================
__global__ __launch_bounds__(256) void qkv_gemm_k(
    const float* __restrict__ x,
    const float* __restrict__ wq,
    const float* __restrict__ wkv)
{
    __shared__ float As[2][16][128];
    __shared__ float Bs[2][16][128];

    const int pT  = blockIdx.x * 128;
    const int oT  = blockIdx.y * 128;
    const int b   = blockIdx.z;
    const int tid = threadIdx.x;
    const int m0  = (tid >> 4) * 4;
    const int n0  = (tid & 15) * 4;

    const float* xb = x + (size_t)b * C_ * P_;

    // A-load coords: two float4 rows
    const int ka0 = tid >> 5;             // 0..7
    const int ma4 = (tid & 31) << 2;      // 0..124
    // B-load coords
    const int ol0 = tid >> 2;
    const int ol1 = ol0 + 64;
    const int k4  = (tid & 3) << 2;
    const int or0 = oT + ol0;
    const int or1 = oT + ol1;
    const float* wr0 = (or0 < 256) ? (wq + or0 * 256) : (wkv + (or0 - 256) * 256);
    const float* wr1 = (or1 < 256) ? (wq + or1 * 256) : (wkv + (or1 - 256) * 256);

    float acc[8][8];
#pragma unroll
    for (int i = 0; i < 8; i++)
#pragma unroll
        for (int j = 0; j < 8; j++) acc[i][j] = 0.f;

    float4 ra0, ra1, rb0, rb1;

#define QKV_LOADG(K0)                                                          \
    {                                                                          \
        ra0 = *(const float4*)&xb[(size_t)((K0) + ka0) * P_ + pT + ma4];       \
        ra1 = *(const float4*)&xb[(size_t)((K0) + 8 + ka0) * P_ + pT + ma4];   \
        rb0 = *(const float4*)&wr0[(K0) + k4];                                 \
        rb1 = *(const float4*)&wr1[(K0) + k4];                                 \
    }
#define QKV_STORE(BUF)                                                         \
    {                                                                          \
        *(float4*)&As[BUF][ka0][ma4]     = ra0;                                \
        *(float4*)&As[BUF][8 + ka0][ma4] = ra1;                                \
        Bs[BUF][k4 + 0][ol0] = rb0.x; Bs[BUF][k4 + 1][ol0] = rb0.y;            \
        Bs[BUF][k4 + 2][ol0] = rb0.z; Bs[BUF][k4 + 3][ol0] = rb0.w;            \
        Bs[BUF][k4 + 0][ol1] = rb1.x; Bs[BUF][k4 + 1][ol1] = rb1.y;            \
        Bs[BUF][k4 + 2][ol1] = rb1.z; Bs[BUF][k4 + 3][ol1] = rb1.w;            \
    }

    QKV_LOADG(0);
    QKV_STORE(0);
    __syncthreads();

    for (int it = 0; it < 16; it++) {
        const int buf = it & 1;
        if (it < 15) QKV_LOADG((it + 1) * 16);
#pragma unroll
        for (int kk = 0; kk < 16; kk++) {
            float4 a0 = *(float4*)&As[buf][kk][m0];
            float4 a1 = *(float4*)&As[buf][kk][m0 + 64];
            float4 b0 = *(float4*)&Bs[buf][kk][n0];
            float4 b1 = *(float4*)&Bs[buf][kk][n0 + 64];
            float a[8] = {a0.x, a0.y, a0.z, a0.w, a1.x, a1.y, a1.z, a1.w};
            float bb[8] = {b0.x, b0.y, b0.z, b0.w, b1.x, b1.y, b1.z, b1.w};
#pragma unroll
            for (int i = 0; i < 8; i++)
#pragma unroll
                for (int j = 0; j < 8; j++) acc[i][j] += a[i] * bb[j];
        }
        if (it < 15) {
            QKV_STORE(buf ^ 1);
            __syncthreads();
        }
    }

#pragma unroll
    for (int i = 0; i < 8; i++) {
        int m = (i < 4) ? (m0 + i) : (m0 + 64 + (i - 4));
        float* orow = &g_qkv[((size_t)b * P_ + pT + m) * 768 + oT];
        *(float4*)&orow[n0]      = make_float4(acc[i][0], acc[i][1], acc[i][2], acc[i][3]);
        *(float4*)&orow[n0 + 64] = make_float4(acc[i][4], acc[i][5], acc[i][6], acc[i][7]);
    }
}

// =====================================================================
// Kernel 2: halo attention. One CTA per (batch, block). 512 threads.
// =====================================================================
// smem layout (floats)
#define OQ_   0                                 // 64*36
#define OK_   (OQ_ + 64 * KST_)                 // 224*36
#define OV_   (OK_ + NKPAD_ * KST_)             // 196*36
#define OS_   (OV_ + 196 * KST_)                // 64*197
#define OSC_  (OS_ + 64 * 197)                  // 4096 scratch
#define OBW_  (OSC_ + 4096)                     // 896
#define OBH_  (OBW_ + 896)                      // 896
#define ORH_  (OBH_ + 896)                      // 864
#define ORW_  (ORH_ + 864)                      // 864
#define SMEMF_ (ORW_ + 864)

__global__ __launch_bounds__(512) void halo_attn_k(
    const float* __restrict__ rel_h,
    const float* __restrict__ rel_w)
{
    extern __shared__ float sm[];
    float* sQ  = sm + OQ_;
    float* sK  = sm + OK_;
    float* sV  = sm + OV_;
    float* sS  = sm + OS_;
    float* sSC = sm + OSC_;
    float* sBW = sm + OBW_;
    float* sBH = sm + OBH_;
    float* sRH = sm + ORH_;
    float* sRW = sm + ORW_;

    const int b    = blockIdx.y;
    const int blk  = blockIdx.x;
    const int bh   = blk >> 4;
    const int bw   = blk & 15;
    const int tid  = threadIdx.x;
    const int w    = tid >> 5;
    const int lane = tid & 31;
    const float scale = 0.1767766952966369f;  // 1/sqrt(32)

    // rel tables + zero K pad rows (once)
    for (int i = tid; i < 27 * 32; i += 512) {
        sRH[i] = rel_h[i];
        sRW[i] = rel_w[i];
    }
    for (int i = tid; i < (NKPAD_ - NKEY_) * KST_; i += 512)
        sK[NKEY_ * KST_ + i] = 0.f;

    for (int hd = 0; hd < HEADS_; hd++) {
        __syncthreads();  // protects smem reuse across heads (and init)

        // ---- load Q: 64 rows x 32 (float4) ----
        {
            int r = tid >> 3, d4 = (tid & 7) << 2;
            int p = (bh * 8 + (r >> 3)) * 128 + bw * 8 + (r & 7);
            float4 v = *(const float4*)&g_qkv[((size_t)b * P_ + p) * 768 + hd * 32 + d4];
            *(float4*)&sQ[r * KST_ + d4] = v;
        }
        // ---- load K,V: 196 rows x 32 each (float4, zero-pad halo) ----
        for (int idx = tid; idx < NKEY_ * 16; idx += 512) {
            int r = idx >> 4, rem = idx & 15;
            int arr = rem >> 3, d4 = (rem & 7) << 2;
            int iw = r / 14, jw = r - iw * 14;
            int hp = bh * 8 - HALO_ + iw;
            int wp = bw * 8 - HALO_ + jw;
            float4 v = make_float4(0.f, 0.f, 0.f, 0.f);
            if (hp >= 0 && hp < H_ && wp >= 0 && wp < W_)
                v = *(const float4*)&g_qkv[((size_t)b * P_ + hp * 128 + wp) * 768
                                           + 256 + arr * 256 + hd * 32 + d4];
            float* dst = arr ? sV : sK;
            *(float4*)&dst[r * KST_ + d4] = v;
        }
        __syncthreads();

        // ---- rel-pos bias (vectorized) ----
        for (int idx = tid; idx < 64 * 14; idx += 512) {
            int qi = idx / 14, j = idx - qi * 14;
            int xq = qi >> 3, yq = qi & 7;
            const float4* qr = (const float4*)(sQ + qi * KST_);
            const float4* rw = (const float4*)(sRW + (j - yq + 13) * 32);
            const float4* rh = (const float4*)(sRH + (j - xq + 13) * 32);
            float aw = 0.f, ah = 0.f;
#pragma unroll
            for (int d = 0; d < 8; d++) {
                float4 q = qr[d], a = rw[d], c = rh[d];
                aw += q.x * a.x + q.y * a.y + q.z * a.z + q.w * a.w;
                ah += q.x * c.x + q.y * c.y + q.z * c.z + q.w * c.w;
            }
            sBW[idx] = aw;
            sBH[idx] = ah;
        }
        __syncthreads();

        // ---- scores: 4q x 7k per thread, float4 over d ----
        {
            const int q0 = (w >> 2) * 16 + (lane >> 3) * 4;
            const int k0 = (w & 3) * 56 + (lane & 7) * 7;
            float acc[4][7];
#pragma unroll
            for (int i = 0; i < 4; i++)
#pragma unroll
                for (int j = 0; j < 7; j++) acc[i][j] = 0.f;

#pragma unroll
            for (int ds = 0; ds < 8; ds++) {
                int d = ds * 4;
                float4 qv[4], kv[7];
#pragma unroll
                for (int i = 0; i < 4; i++) qv[i] = *(float4*)&sQ[(q0 + i) * KST_ + d];
#pragma unroll
                for (int j = 0; j < 7; j++) kv[j] = *(float4*)&sK[(k0 + j) * KST_ + d];
#pragma unroll
                for (int i = 0; i < 4; i++)
#pragma unroll
                    for (int j = 0; j < 7; j++)
                        acc[i][j] += qv[i].x * kv[j].x + qv[i].y * kv[j].y
                                   + qv[i].z * kv[j].z + qv[i].w * kv[j].w;
            }
#pragma unroll
            for (int i = 0; i < 4; i++) {
                int qi = q0 + i;
#pragma unroll
                for (int j = 0; j < 7; j++) {
                    int kj = k0 + j;
                    if (kj < NKEY_) {
                        int r14 = kj / 14;
                        int c14 = kj - r14 * 14;
                        sS[qi * 197 + kj] = acc[i][j] * scale
                                          + sBW[qi * 14 + c14]
                                          + sBH[qi * 14 + r14];
                    }
                }
            }
        }
        __syncthreads();

        // ---- softmax per row (16 warps x 4 rows) ----
        for (int r = w * 4; r < w * 4 + 4; r++) {
            float* row = sS + r * 197;
            float m = -1e30f;
            for (int c = lane; c < NKEY_; c += 32) m = fmaxf(m, row[c]);
#pragma unroll
            for (int o = 16; o; o >>= 1) m = fmaxf(m, __shfl_xor_sync(0xffffffffu, m, o));
            float s = 0.f;
            for (int c = lane; c < NKEY_; c += 32) {
                float e = __expf(row[c] - m);
                row[c] = e;
                s += e;
            }
#pragma unroll
            for (int o = 16; o; o >>= 1) s += __shfl_xor_sync(0xffffffffu, s, o);
            float inv = 1.f / s;
            for (int c = lane; c < NKEY_; c += 32) row[c] *= inv;
        }
        __syncthreads();

        // ---- ctx: 2q x 4d per thread, split-K (2 groups x 98 keys) ----
        {
            const int g  = tid >> 8;
            const int t  = tid & 255;
            const int q0 = (t >> 3) * 2;
            const int d0 = (t & 7) * 4;
            float a0x = 0.f, a0y = 0.f, a0z = 0.f, a0w = 0.f;
            float a1x = 0.f, a1y = 0.f, a1z = 0.f, a1w = 0.f;
            const float* s0p = sS + q0 * 197;
            const float* s1p = s0p + 197;
            const int kbeg = g * 98;
#pragma unroll 2
            for (int k = kbeg; k < kbeg + 98; k++) {
                float s0 = s0p[k];
                float s1 = s1p[k];
                float4 v = *(float4*)&sV[k * KST_ + d0];
                a0x += s0 * v.x; a0y += s0 * v.y; a0z += s0 * v.z; a0w += s0 * v.w;
                a1x += s1 * v.x; a1y += s1 * v.y; a1z += s1 * v.z; a1w += s1 * v.w;
            }
            *(float4*)&sSC[g * 2048 + t * 8]     = make_float4(a0x, a0y, a0z, a0w);
            *(float4*)&sSC[g * 2048 + t * 8 + 4] = make_float4(a1x, a1y, a1z, a1w);
        }
        __syncthreads();

        // ---- reduce partials + store channel-major ----
        {
            int idx = tid * 4;                    // 0..2044
            float4 p0 = *(float4*)&sSC[idx];
            float4 p1 = *(float4*)&sSC[2048 + idx];
            float r0 = p0.x + p1.x, r1 = p0.y + p1.y;
            float r2 = p0.z + p1.z, r3 = p0.w + p1.w;
            int t2 = idx >> 3;
            int i  = (idx >> 2) & 1;
            int q  = (t2 >> 3) * 2 + i;
            int d0 = (t2 & 7) * 4;
            int p  = (bh * 8 + (q >> 3)) * 128 + bw * 8 + (q & 7);
            size_t cb = ((size_t)b * C_ + hd * 32 + d0) * P_ + p;
            g_ctx[cb]          = r0;
            g_ctx[cb + P_]     = r1;
            g_ctx[cb + 2 * P_] = r2;
            g_ctx[cb + 3 * P_] = r3;
        }
    }
}

// =====================================================================
// Kernel 3: FC epilogue, ping-pong. out[b][o][p] = fc_w[o][:]·ctx[b][:][p]+b[o]
// BM=64 (o), BN=128 (p), BK=16, 256 threads, 4x8 microtile.
// =====================================================================
__global__ __launch_bounds__(256) void fc_gemm_k(
    const float* __restrict__ fcw,
    const float* __restrict__ fcb,
    float* __restrict__ out)
{
    __shared__ float As[2][16][64];
    __shared__ float Bs[2][16][128];

    const int pT  = blockIdx.x * 128;
    const int oT  = blockIdx.y * 64;
    const int b   = blockIdx.z;
    const int tid = threadIdx.x;
    const int m0  = (tid >> 4) * 4;
    const int n0  = (tid & 15) * 4;

    const int am = tid & 63;
    const int ak = (tid >> 6) * 4;
    const int kb0 = tid >> 5;
    const int nb4 = (tid & 31) << 2;
    const float* arow = fcw + (oT + am) * 256;
    const float* ctxb = g_ctx + (size_t)b * C_ * P_;

    float acc[4][8];
#pragma unroll
    for (int i = 0; i < 4; i++)
#pragma unroll
        for (int j = 0; j < 8; j++) acc[i][j] = 0.f;

    float4 ra, rb0, rb1;

#define FC_LOADG(K0)                                                           \
    {                                                                          \
        ra  = *(const float4*)&arow[(K0) + ak];                                \
        rb0 = *(const float4*)&ctxb[(size_t)((K0) + kb0) * P_ + pT + nb4];     \
        rb1 = *(const float4*)&ctxb[(size_t)((K0) + 8 + kb0) * P_ + pT + nb4]; \
    }
#define FC_STORE(BUF)                                                          \
    {                                                                          \
        As[BUF][ak + 0][am] = ra.x; As[BUF][ak + 1][am] = ra.y;                \
        As[BUF][ak + 2][am] = ra.z; As[BUF][ak + 3][am] = ra.w;                \
        *(float4*)&Bs[BUF][kb0][nb4]     = rb0;                                \
        *(float4*)&Bs[BUF][8 + kb0][nb4] = rb1;                                \
    }

    FC_LOADG(0);
    FC_STORE(0);
    __syncthreads();

    for (int it = 0; it < 16; it++) {
        const int buf = it & 1;
        if (it < 15) FC_LOADG((it + 1) * 16);
#pragma unroll
        for (int kk = 0; kk < 16; kk++) {
            float4 av = *(float4*)&As[buf][kk][m0];
            float4 b0 = *(float4*)&Bs[buf][kk][n0];
            float4 b1 = *(float4*)&Bs[buf][kk][n0 + 64];
            float a[4] = {av.x, av.y, av.z, av.w};
            float bb[8] = {b0.x, b0.y, b0.z, b0.w, b1.x, b1.y, b1.z, b1.w};
#pragma unroll
            for (int i = 0; i < 4; i++)
#pragma unroll
                for (int j = 0; j < 8; j++) acc[i][j] += a[i] * bb[j];
        }
        if (it < 15) {
            FC_STORE(buf ^ 1);
            __syncthreads();
        }
    }

#pragma unroll
    for (int i = 0; i < 4; i++) {
        int o = oT + m0 + i;
        float bias = fcb[o];
        float* orow = out + ((size_t)b * C_ + o) * P_ + pT;
        *(float4*)&orow[n0]      = make_float4(acc[i][0] + bias, acc[i][1] + bias,
                                               acc[i][2] + bias, acc[i][3] + bias);
        *(float4*)&orow[n0 + 64] = make_float4(acc[i][4] + bias, acc[i][5] + bias,
                                               acc[i][6] + bias, acc[i][7] + bias);
    }
}

// =====================================================================
extern "C" void kernel_launch(void* const* d_in, const int* in_sizes, int n_in,
                              void* d_out, int out_size)
{
    const float* x   = (const float*)d_in[0];
    const float* wq  = (const float*)d_in[1];
    const float* wkv = (const float*)d_in[2];
    const float* fcw = (const float*)d_in[3];
    const float* fcb = (const float*)d_in[4];
    const float* rh  = (const float*)d_in[5];
    const float* rw  = (const float*)d_in[6];
    float* out = (float*)d_out;

    cudaFuncSetAttribute(halo_attn_k,
                         cudaFuncAttributeMaxDynamicSharedMemorySize,
                         SMEMF_ * (int)sizeof(float));

    qkv_gemm_k<<<dim3(P_ / 128, 6, B_), 256>>>(x, wq, wkv);
    halo_attn_k<<<dim3(NB_, B_), 512, SMEMF_ * sizeof(float)>>>(rh, rw);
    fc_gemm_k<<<dim3(P_ / 128, C_ / 64, B_), 256>>>(fcw, fcb, out);
}